// round 6
// baseline (speedup 1.0000x reference)
#include <cuda_runtime.h>
#include <stdint.h>

#define NSBIN     4096            // sampled (coarse) histogram bins: key = bits>>19
#define NFBIN     8192            // fine histogram bins: key = (bits>>12) - (pivot<<7)
#define CAND_CAP  (16*1024*1024)
#define CAP2      65536
#define SBUF_CAP  1024
#define LAST_DIM  16384

// ---------------- persistent device state (cleared every launch) ----------------
__device__ int                g_shist[NSBIN];
__device__ int                g_fhist[NFBIN];
__device__ unsigned long long g_cand[CAND_CAP];
__device__ unsigned long long g_cand2[CAP2];
__device__ int g_cand_n, g_cand2_n;
__device__ int g_pivot;           // coarse pivot in bits>>19 space
__device__ int g_bstar, g_need;   // fine cutoff bin (offset space) + count needed inside it
__device__ int g_done_s, g_done_h;

// ---------------- init ----------------
__global__ void k_init() {
    int i = blockIdx.x * blockDim.x + threadIdx.x;
    int stride = gridDim.x * blockDim.x;
    for (int j = i; j < NFBIN; j += stride) g_fhist[j] = 0;
    if (i < NSBIN) g_shist[i] = 0;
    if (i == 0) {
        g_cand_n = 0; g_cand2_n = 0;
        g_pivot = 1;
        g_bstar = 0x7fffffff; g_need = 0;
        g_done_s = 0; g_done_h = 0;
    }
}

// ---------------- generic in-block suffix-boundary finder ---------------------
// hist has NB bins, NB = 1024 * PER. Finds b: suffix(b) >= target > suffix(b+1).
template <int PER>
__device__ void suffix_find_t(const int* hist, long long target, int& b_out, int& after_out) {
    __shared__ int ssum[1024];
    __shared__ int sh_b, sh_after;
    int t = threadIdx.x;
    if (t == 0) { sh_b = -1; sh_after = 0; }
    int h[PER];
    int b0 = PER * t;
    #pragma unroll
    for (int q = 0; q < PER; q++) h[q] = hist[b0 + q];
    int loc[PER + 1];
    loc[PER] = 0;
    #pragma unroll
    for (int q = PER - 1; q >= 0; q--) loc[q] = loc[q + 1] + h[q];
    ssum[t] = loc[0];
    __syncthreads();
    for (int off = 1; off < 1024; off <<= 1) {
        int v = (t + off < 1024) ? ssum[t + off] : 0;
        __syncthreads();
        ssum[t] += v;
        __syncthreads();
    }
    int after = (t + 1 < 1024) ? ssum[t + 1] : 0;
    #pragma unroll
    for (int q = 0; q < PER; q++) {
        long long shi = (long long)loc[q] + after;
        long long slo = (long long)loc[q + 1] + after;
        if (shi >= target && slo < target) { sh_b = b0 + q; sh_after = (int)slo; }
    }
    __syncthreads();
    b_out = sh_b; after_out = sh_after;
}

// ---------------- sampled histogram + fused pivot find ------------------------
__global__ void __launch_bounds__(1024) k_sample(const float4* __restrict__ x, int nchunk,
                                                 const int* kptr, int num_samples) {
    __shared__ int h[NSBIN];
    __shared__ int sh_last;
    for (int j = threadIdx.x; j < NSBIN; j += blockDim.x) h[j] = 0;
    __syncthreads();
    int gw   = (blockIdx.x * blockDim.x + threadIdx.x) >> 5;
    int lane = threadIdx.x & 31;
    int nw   = (gridDim.x * blockDim.x) >> 5;
    for (int c = gw; c < nchunk; c += nw) {
        float4 v = x[(size_t)c * 2048 + lane];
        int b0 = __float_as_int(v.x), b1 = __float_as_int(v.y);
        int b2 = __float_as_int(v.z), b3 = __float_as_int(v.w);
        if (b0 > 0) atomicAdd(&h[b0 >> 19], 1);
        if (b1 > 0) atomicAdd(&h[b1 >> 19], 1);
        if (b2 > 0) atomicAdd(&h[b2 >> 19], 1);
        if (b3 > 0) atomicAdd(&h[b3 >> 19], 1);
    }
    __syncthreads();
    for (int j = threadIdx.x; j < NSBIN; j += blockDim.x) {
        int c = h[j];
        if (c) atomicAdd(&g_shist[j], c);
    }
    __threadfence();
    if (threadIdx.x == 0)
        sh_last = (atomicAdd(&g_done_s, 1) == (int)gridDim.x - 1);
    __syncthreads();
    if (sh_last) {
        int kk = (kptr != nullptr) ? kptr[0] : 64;
        long long nk = (long long)kk * num_samples;
        long long target = (nk * 135) / (100 * 64) + 256;  // 1.35x expected + slack
        if (target < 1) target = 1;
        int b, after;
        suffix_find_t<4>(g_shist, target, b, after);
        if (threadIdx.x == 0) g_pivot = (b >= 1) ? b : 1;
    }
}

// ---------------- candidate push helper ----------------
__device__ __forceinline__ void push_cand(unsigned bits, unsigned idx,
                                          int* s_cnt, unsigned long long* s_buf) {
    unsigned long long pk = ((unsigned long long)bits << 32) | (unsigned long long)idx;
    int sl = atomicAdd(s_cnt, 1);
    if (sl < SBUF_CAP) {
        s_buf[sl] = pk;
    } else {
        int p = atomicAdd(&g_cand_n, 1);
        if (p < CAND_CAP) g_cand[p] = pk;
    }
}

// ---------------- main pass: zero out, collect candidates (coalesced) ----------
__global__ void __launch_bounds__(256) k_main(const float4* __restrict__ x,
                                              float4* __restrict__ out, int n4) {
    __shared__ int s_cnt;
    __shared__ int s_base;
    __shared__ unsigned long long s_buf[SBUF_CAP];
    if (threadIdx.x == 0) s_cnt = 0;
    __syncthreads();

    const float pv = __int_as_float(g_pivot << 19);
    const float4 Z = make_float4(0.f, 0.f, 0.f, 0.f);
    int t = threadIdx.x;
    int ntile = n4 >> 10;

    for (int tile = blockIdx.x; tile < ntile; tile += gridDim.x) {
        int base = tile << 10;
        float4 v0 = x[base + t];
        float4 v1 = x[base + 256 + t];
        float4 v2 = x[base + 512 + t];
        float4 v3 = x[base + 768 + t];
        out[base + t]       = Z;
        out[base + 256 + t] = Z;
        out[base + 512 + t] = Z;
        out[base + 768 + t] = Z;
        float m0 = fmaxf(fmaxf(v0.x, v0.y), fmaxf(v0.z, v0.w));
        float m1 = fmaxf(fmaxf(v1.x, v1.y), fmaxf(v1.z, v1.w));
        float m2 = fmaxf(fmaxf(v2.x, v2.y), fmaxf(v2.z, v2.w));
        float m3 = fmaxf(fmaxf(v3.x, v3.y), fmaxf(v3.z, v3.w));
        if (fmaxf(fmaxf(m0, m1), fmaxf(m2, m3)) >= pv) {
            float4 vv[4] = {v0, v1, v2, v3};
            #pragma unroll
            for (int q = 0; q < 4; q++) {
                unsigned fidx = (unsigned)(base + q * 256 + t) * 4u;
                float e[4] = {vv[q].x, vv[q].y, vv[q].z, vv[q].w};
                #pragma unroll
                for (int c = 0; c < 4; c++) {
                    if (e[c] >= pv)
                        push_cand(__float_as_uint(e[c]), fidx + c, &s_cnt, s_buf);
                }
            }
        }
    }
    for (int j = (ntile << 10) + blockIdx.x * blockDim.x + t; j < n4;
         j += gridDim.x * blockDim.x) {
        float4 v = x[j];
        out[j] = Z;
        float e[4] = {v.x, v.y, v.z, v.w};
        #pragma unroll
        for (int c = 0; c < 4; c++) {
            if (e[c] >= pv)
                push_cand(__float_as_uint(e[c]), (unsigned)j * 4u + c, &s_cnt, s_buf);
        }
    }
    __syncthreads();
    int cnt = s_cnt; if (cnt > SBUF_CAP) cnt = SBUF_CAP;
    if (threadIdx.x == 0) s_base = atomicAdd(&g_cand_n, cnt);
    __syncthreads();
    for (int q = threadIdx.x; q < cnt; q += blockDim.x) {
        int sl = s_base + q;
        if (sl < CAND_CAP) g_cand[sl] = s_buf[q];
    }
}

// ---------------- fine histogram over candidates + fused threshold find --------
__global__ void __launch_bounds__(1024) k_hist(const int* kptr, int num_samples) {
    __shared__ int h[NFBIN];
    __shared__ int sh_last;
    for (int j = threadIdx.x; j < NFBIN; j += blockDim.x) h[j] = 0;
    __syncthreads();
    int base_key = g_pivot << 7;
    int cn = g_cand_n; if (cn > CAND_CAP) cn = CAND_CAP;
    int i = blockIdx.x * blockDim.x + threadIdx.x;
    int stride = gridDim.x * blockDim.x;
    for (; i < cn; i += stride) {
        int key = (int)(g_cand[i] >> 44) - base_key;   // bits >> 12, rebased
        if (key < 0) key = 0;
        if (key >= NFBIN) key = NFBIN - 1;
        atomicAdd(&h[key], 1);
    }
    __syncthreads();
    for (int j = threadIdx.x; j < NFBIN; j += blockDim.x) {
        int c = h[j];
        if (c) atomicAdd(&g_fhist[j], c);
    }
    __threadfence();
    if (threadIdx.x == 0)
        sh_last = (atomicAdd(&g_done_h, 1) == (int)gridDim.x - 1);
    __syncthreads();
    if (sh_last) {
        int kk = (kptr != nullptr) ? kptr[0] : 64;
        long long nk = (long long)kk * num_samples;
        if (nk > cn) nk = cn;
        if (nk <= 0) return;
        int b, after;
        suffix_find_t<8>(g_fhist, nk, b, after);
        if (threadIdx.x == 0 && b >= 0) {
            g_bstar = b;
            g_need  = (int)(nk - after);
        }
    }
}

// ---------------- write winners / collect exact-bin ties ----------------------
__global__ void k_write(float* __restrict__ out) {
    int bstar = g_bstar;
    int base_key = g_pivot << 7;
    int cn = g_cand_n; if (cn > CAND_CAP) cn = CAND_CAP;
    int i = blockIdx.x * blockDim.x + threadIdx.x;
    int stride = gridDim.x * blockDim.x;
    for (; i < cn; i += stride) {
        unsigned long long p = g_cand[i];
        int key = (int)(p >> 44) - base_key;
        if (key < 0) key = 0;
        if (key >= NFBIN) key = NFBIN - 1;
        if (key > bstar) {
            out[(unsigned)p] = __uint_as_float((unsigned)(p >> 32));
        } else if (key == bstar) {
            int s = atomicAdd(&g_cand2_n, 1);
            if (s < CAP2) g_cand2[s] = p;
        }
    }
}

// ---------------- exact tie-break in the cutoff bin ---------------------------
__global__ void k_res(float* __restrict__ out) {
    int n = g_cand2_n; if (n > CAP2) n = CAP2;
    int need = g_need;
    if (need <= 0) return;
    int i = blockIdx.x * blockDim.x + threadIdx.x;
    int stride = gridDim.x * blockDim.x;
    for (; i < n; i += stride) {
        unsigned long long ci = g_cand2[i];
        unsigned bi = (unsigned)(ci >> 32), ii = (unsigned)ci;
        int rank = 0;
        for (int jj = 0; jj < n; jj++) {
            unsigned long long cj = g_cand2[jj];
            unsigned bj = (unsigned)(cj >> 32), ij = (unsigned)cj;
            rank += (bj > bi) || (bj == bi && ij < ii);
        }
        if (rank < need) out[ii] = __uint_as_float(bi);
    }
}

// ---------------- launch ----------------
extern "C" void kernel_launch(void* const* d_in, const int* in_sizes, int n_in,
                              void* d_out, int out_size) {
    const float* x  = (const float*)d_in[0];
    const int* kptr = (n_in >= 2) ? (const int*)d_in[1] : nullptr;
    float* out      = (float*)d_out;

    int n  = in_sizes[0];
    int n4 = n / 4;
    int nchunk = n4 / 2048;
    int num_samples = n / LAST_DIM;

    k_init  <<<32, 256>>>();
    k_sample<<<148, 1024>>>((const float4*)x, nchunk, kptr, num_samples);
    k_main  <<<2048, 256>>>((const float4*)x, (float4*)out, n4);
    k_hist  <<<148, 1024>>>(kptr, num_samples);
    k_write <<<512, 256>>>(out);
    k_res   <<<64, 256>>>(out);
}